// round 1
// baseline (speedup 1.0000x reference)
#include <cuda_runtime.h>
#include <cuda_bf16.h>

#define NA   65536
#define D    256
#define TT   4
#define TM   64
#define KT   8
#define NKT  (D / KT)     // 32
#define NTH  256
#define SMEM_BYTES ((2 * TM * D + 2 * KT * D) * 4)   // 147456 = 144KB

// ---------------- scratch (no allocations allowed) ----------------
__device__ int nn_off[TT + 1];
__device__ int nn_cnt[TT];
__device__ int nn_cur[TT];
__device__ int nn_perm[NA];

// ---------------- sort-by-species pipeline ----------------
__global__ void nn_init() {
    int t = threadIdx.x;
    if (t < TT) { nn_cnt[t] = 0; nn_cur[t] = 0; }
}

__global__ void nn_hist(const int* __restrict__ sp) {
    __shared__ int c[TT];
    int tid = threadIdx.x;
    if (tid < TT) c[tid] = 0;
    __syncthreads();
    int i = blockIdx.x * blockDim.x + tid;
    if (i < NA) atomicAdd(&c[sp[i]], 1);
    __syncthreads();
    if (tid < TT && c[tid] > 0) atomicAdd(&nn_cnt[tid], c[tid]);
}

__global__ void nn_prefix() {
    if (threadIdx.x == 0) {
        int a = 0;
        for (int s = 0; s < TT; s++) { nn_off[s] = a; a += nn_cnt[s]; }
        nn_off[TT] = a;
    }
}

__global__ void nn_scatter(const int* __restrict__ sp) {
    __shared__ int lc[TT];     // local counts
    __shared__ int lb[TT];     // global base for this block
    int tid = threadIdx.x;
    if (tid < TT) lc[tid] = 0;
    __syncthreads();
    int i = blockIdx.x * blockDim.x + tid;
    int s = 0, pos = 0;
    if (i < NA) {
        s = sp[i];
        pos = atomicAdd(&lc[s], 1);
    }
    __syncthreads();
    if (tid < TT) {
        int n = lc[tid];
        lb[tid] = (n > 0) ? atomicAdd(&nn_cur[tid], n) : 0;
    }
    __syncthreads();
    if (i < NA) {
        nn_perm[nn_off[s] + lb[s] + pos] = i;
    }
}

// ---------------- helpers ----------------
__device__ __forceinline__ unsigned long long nn_pack2(float lo, float hi) {
    unsigned long long r;
    asm("mov.b64 %0, {%1, %2};" : "=l"(r) : "f"(lo), "f"(hi));
    return r;
}
__device__ __forceinline__ void nn_fma2(unsigned long long& d,
                                        unsigned long long a,
                                        unsigned long long b) {
    asm("fma.rn.f32x2 %0, %1, %2, %0;" : "+l"(d) : "l"(a), "l"(b));
}
__device__ __forceinline__ float2 nn_unpack2(unsigned long long v) {
    float lo, hi;
    asm("mov.b64 {%0, %1}, %2;" : "=f"(lo), "=f"(hi) : "l"(v));
    return make_float2(lo, hi);
}
__device__ __forceinline__ void nn_load8(const float* __restrict__ p, float v[8]) {
    float4 a = *(const float4*)p;
    float4 b = *(const float4*)(p + 4);
    v[0] = a.x; v[1] = a.y; v[2] = a.z; v[3] = a.w;
    v[4] = b.x; v[5] = b.y; v[6] = b.z; v[7] = b.w;
}
__device__ __forceinline__ float nn_wsum(float v) {
#pragma unroll
    for (int o = 16; o; o >>= 1) v += __shfl_xor_sync(0xffffffffu, v, o);
    return v;
}

// out[r][c] = sum_k src[r][k] * Wg[c*D + k], tile 64x256, K=256.
// src: smem [TM][D]. wt: smem double buffer [2][KT][D] (k-major).
// Thread (warp w, lane l) owns rows w*8..w*8+7, cols l*8..l*8+7.
// Ends WITHOUT a trailing __syncthreads() — caller must sync before
// touching src or wt.
__device__ __forceinline__ void nn_gemm(const float* __restrict__ Wg,
                                        const float* __restrict__ src,
                                        float* __restrict__ wt,
                                        float acc[8][8],
                                        int warp, int lane, int tid) {
    unsigned long long acc2[8][4];
#pragma unroll
    for (int i = 0; i < 8; i++)
#pragma unroll
        for (int p = 0; p < 4; p++) acc2[i][p] = 0ull;

    // preload tile 0 (transpose: wt[k][j] = W[j][k])
    {
        float4 a = *(const float4*)(Wg + tid * D);
        float4 b = *(const float4*)(Wg + tid * D + 4);
        wt[0 * D + tid] = a.x; wt[1 * D + tid] = a.y;
        wt[2 * D + tid] = a.z; wt[3 * D + tid] = a.w;
        wt[4 * D + tid] = b.x; wt[5 * D + tid] = b.y;
        wt[6 * D + tid] = b.z; wt[7 * D + tid] = b.w;
    }
    __syncthreads();

    for (int kt = 0; kt < NKT; kt++) {
        int cur = kt & 1;
        float4 la = make_float4(0.f, 0.f, 0.f, 0.f);
        float4 lb = make_float4(0.f, 0.f, 0.f, 0.f);
        if (kt + 1 < NKT) {
            la = *(const float4*)(Wg + tid * D + (kt + 1) * KT);
            lb = *(const float4*)(Wg + tid * D + (kt + 1) * KT + 4);
        }
        const float* w = wt + cur * (KT * D);
        const int kbase = kt * KT;
#pragma unroll
        for (int ku = 0; ku < KT; ku += 4) {
            float4 xv[8];
#pragma unroll
            for (int i = 0; i < 8; i++)
                xv[i] = *(const float4*)(src + (warp * 8 + i) * D + kbase + ku);
#pragma unroll
            for (int u = 0; u < 4; u++) {
                float4 w0 = *(const float4*)(w + (ku + u) * D + lane * 8);
                float4 w1 = *(const float4*)(w + (ku + u) * D + lane * 8 + 4);
                unsigned long long wp[4];
                wp[0] = nn_pack2(w0.x, w0.y);
                wp[1] = nn_pack2(w0.z, w0.w);
                wp[2] = nn_pack2(w1.x, w1.y);
                wp[3] = nn_pack2(w1.z, w1.w);
#pragma unroll
                for (int i = 0; i < 8; i++) {
                    float xk = (u == 0) ? xv[i].x : (u == 1) ? xv[i].y
                              : (u == 2) ? xv[i].z : xv[i].w;
                    unsigned long long xp = nn_pack2(xk, xk);
#pragma unroll
                    for (int p = 0; p < 4; p++) nn_fma2(acc2[i][p], xp, wp[p]);
                }
            }
        }
        if (kt + 1 < NKT) {
            float* wn = wt + (1 - cur) * (KT * D);
            wn[0 * D + tid] = la.x; wn[1 * D + tid] = la.y;
            wn[2 * D + tid] = la.z; wn[3 * D + tid] = la.w;
            wn[4 * D + tid] = lb.x; wn[5 * D + tid] = lb.y;
            wn[6 * D + tid] = lb.z; wn[7 * D + tid] = lb.w;
            __syncthreads();
        }
    }
#pragma unroll
    for (int i = 0; i < 8; i++)
#pragma unroll
        for (int p = 0; p < 4; p++) {
            float2 f = nn_unpack2(acc2[i][p]);
            acc[i][2 * p]     = f.x;
            acc[i][2 * p + 1] = f.y;
        }
}

// ---------------- fused expert MLP over sorted tiles ----------------
__global__ void __launch_bounds__(NTH, 1)
nn_fused(const float* __restrict__ density,
         const float* __restrict__ W0, const float* __restrict__ b0,
         const float* __restrict__ Wa, const float* __restrict__ ba,
         const float* __restrict__ alpha_a, const float* __restrict__ gamma,
         const float* __restrict__ beta_ln,
         const float* __restrict__ Wl, const float* __restrict__ bl,
         const float* __restrict__ Wf, const float* __restrict__ bf,
         const float* __restrict__ alpha_f,
         const float* __restrict__ Wo, const float* __restrict__ bo,
         float* __restrict__ out) {
    extern __shared__ float smem[];
    float* xs = smem;                 // [TM][D]
    float* hs = smem + TM * D;        // [TM][D]
    float* wt = smem + 2 * TM * D;    // [2][KT][D]

    const int tid  = threadIdx.x;
    const int warp = tid >> 5;
    const int lane = tid & 31;
    const int row0 = blockIdx.x * TM;
    const int cb   = lane * 8;        // column base
    const int rb   = warp * 8;        // row base (within tile)

    for (int s = 0; s < TT; s++) {
        int lo = max(row0, nn_off[s]);
        int hi = min(row0 + TM, nn_off[s + 1]);
        if (lo >= hi) continue;

        __syncthreads();   // prior iteration fully done with xs/hs/wt
        // gather input rows (zero-pad rows outside [lo, hi))
        for (int idx = tid; idx < TM * (D / 4); idx += NTH) {
            int r  = idx >> 6;        // / (D/4)
            int c4 = idx & 63;
            float4 v = make_float4(0.f, 0.f, 0.f, 0.f);
            int gr = row0 + r;
            if (gr >= lo && gr < hi) {
                int a = nn_perm[gr];
                v = *(const float4*)(density + a * D + c4 * 4);
            }
            *(float4*)(xs + r * D + c4 * 4) = v;
        }
        __syncthreads();

        float acc[8][8];

        // ---- layer 0: x = density @ W0^T + b0  -> xs
        nn_gemm(W0 + s * D * D, xs, wt, acc, warp, lane, tid);
        __syncthreads();
        {
            float bj[8]; nn_load8(b0 + s * D + cb, bj);
#pragma unroll
            for (int i = 0; i < 8; i++) {
                float4 v0 = make_float4(acc[i][0] + bj[0], acc[i][1] + bj[1],
                                        acc[i][2] + bj[2], acc[i][3] + bj[3]);
                float4 v1 = make_float4(acc[i][4] + bj[4], acc[i][5] + bj[5],
                                        acc[i][6] + bj[6], acc[i][7] + bj[7]);
                *(float4*)(xs + (rb + i) * D + cb)     = v0;
                *(float4*)(xs + (rb + i) * D + cb + 4) = v1;
            }
        }
        __syncthreads();

        // ---- hidden: h = LN(alpha_a * silu(x @ Wa^T + ba)) -> hs
        nn_gemm(Wa + s * D * D, xs, wt, acc, warp, lane, tid);
        __syncthreads();
        {
            float bj[8], aj[8], gj[8], btj[8];
            nn_load8(ba      + s * D + cb, bj);
            nn_load8(alpha_a + s * D + cb, aj);
            nn_load8(gamma   + s * D + cb, gj);
            nn_load8(beta_ln + s * D + cb, btj);
#pragma unroll
            for (int i = 0; i < 8; i++) {
                float sum = 0.f;
#pragma unroll
                for (int j = 0; j < 8; j++) {
                    float z  = acc[i][j] + bj[j];
                    float sg = 1.f / (1.f + __expf(-z));
                    float h  = aj[j] * z * sg;
                    acc[i][j] = h;
                    sum += h;
                }
                sum = nn_wsum(sum);
                float mu = sum * (1.f / D);
                float vs = 0.f;
#pragma unroll
                for (int j = 0; j < 8; j++) {
                    float d = acc[i][j] - mu;
                    vs += d * d;
                }
                vs = nn_wsum(vs);
                float inv = rsqrtf(vs * (1.f / D) + 1e-5f);
#pragma unroll
                for (int j = 0; j < 8; j++)
                    acc[i][j] = gj[j] * (acc[i][j] - mu) * inv + btj[j];
                *(float4*)(hs + (rb + i) * D + cb) =
                    make_float4(acc[i][0], acc[i][1], acc[i][2], acc[i][3]);
                *(float4*)(hs + (rb + i) * D + cb + 4) =
                    make_float4(acc[i][4], acc[i][5], acc[i][6], acc[i][7]);
            }
        }
        __syncthreads();

        // ---- residual: x = x + h @ Wl^T + bl   -> xs
        nn_gemm(Wl + s * D * D, hs, wt, acc, warp, lane, tid);
        __syncthreads();
        {
            float bj[8]; nn_load8(bl + s * D + cb, bj);
#pragma unroll
            for (int i = 0; i < 8; i++) {
                float4 o0 = *(const float4*)(xs + (rb + i) * D + cb);
                float4 o1 = *(const float4*)(xs + (rb + i) * D + cb + 4);
                o0.x += acc[i][0] + bj[0]; o0.y += acc[i][1] + bj[1];
                o0.z += acc[i][2] + bj[2]; o0.w += acc[i][3] + bj[3];
                o1.x += acc[i][4] + bj[4]; o1.y += acc[i][5] + bj[5];
                o1.z += acc[i][6] + bj[6]; o1.w += acc[i][7] + bj[7];
                *(float4*)(xs + (rb + i) * D + cb)     = o0;
                *(float4*)(xs + (rb + i) * D + cb + 4) = o1;
            }
        }
        __syncthreads();

        // ---- tail: f = alpha_f * silu(x @ Wf^T + bf); y = f @ Wo^T + bo
        nn_gemm(Wf + s * D * D, xs, wt, acc, warp, lane, tid);
        __syncthreads();
        {
            float bj[8], aj[8], wj[8];
            nn_load8(bf      + s * D + cb, bj);
            nn_load8(alpha_f + s * D + cb, aj);
            nn_load8(Wo      + s * D + cb, wj);
            float bos = bo[s];
#pragma unroll
            for (int i = 0; i < 8; i++) {
                float part = 0.f;
#pragma unroll
                for (int j = 0; j < 8; j++) {
                    float z  = acc[i][j] + bj[j];
                    float sg = 1.f / (1.f + __expf(-z));
                    part += aj[j] * z * sg * wj[j];
                }
                part = nn_wsum(part);
                if (lane == 0) {
                    int gr = row0 + rb + i;
                    if (gr >= lo && gr < hi)
                        out[nn_perm[gr]] = part + bos;
                }
            }
        }
    }
}

// ---------------- launch ----------------
extern "C" void kernel_launch(void* const* d_in, const int* in_sizes, int n_in,
                              void* d_out, int out_size) {
    const float* density = (const float*)d_in[0];
    const int*   species = (const int*)d_in[1];
    const float* W0      = (const float*)d_in[2];
    const float* b0      = (const float*)d_in[3];
    const float* Wa      = (const float*)d_in[4];
    const float* ba      = (const float*)d_in[5];
    const float* alpha_a = (const float*)d_in[6];
    const float* gamma   = (const float*)d_in[7];
    const float* beta_ln = (const float*)d_in[8];
    const float* Wl      = (const float*)d_in[9];
    const float* bl      = (const float*)d_in[10];
    const float* Wf      = (const float*)d_in[11];
    const float* bf      = (const float*)d_in[12];
    const float* alpha_f = (const float*)d_in[13];
    const float* Wo      = (const float*)d_in[14];
    const float* bo      = (const float*)d_in[15];
    float* out = (float*)d_out;

    cudaFuncSetAttribute(nn_fused,
                         cudaFuncAttributeMaxDynamicSharedMemorySize,
                         SMEM_BYTES);

    nn_init<<<1, 32>>>();
    nn_hist<<<NA / 256, 256>>>(species);
    nn_prefix<<<1, 1>>>();
    nn_scatter<<<NA / 256, 256>>>(species);
    nn_fused<<<NA / TM, NTH, SMEM_BYTES>>>(density, W0, b0, Wa, ba, alpha_a,
                                           gamma, beta_ln, Wl, bl, Wf, bf,
                                           alpha_f, Wo, bo, out);
}

// round 3
// speedup vs baseline: 2.8902x; 2.8902x over previous
#include <cuda_runtime.h>
#include <cstdint>

#define NA 65536
#define D  256
#define TT 4
#define TM 64
#define NTILES (NA / TM)   // 1024
#define NTH 256
#define SA 268             // A row stride in floats (pad 12 -> conflict-free frag LDS)

// ---- shared memory float offsets ----
#define OFF_A     0        // uint32 tf32 A tile: 64 x 268         = 17152
#define OFF_B     17152    // B chunk ring: 4 x 4096 floats        = 16384
#define OFF_X     33536    // x residual save: 64 x 256            = 16384
#define OFF_RED   49920    // row partials: [512 sum][512 sq]      = 1024
#define OFF_STATS 50944    // [64][2] mu, inv                      = 128
#define SMEM_FLOATS 51072
#define SMEM_BYTES (SMEM_FLOATS * 4)   // 204288

// ---------------- device scratch ----------------
__device__ int nn_off[TT + 1];
__device__ int nn_cnt[TT];
__device__ int nn_cur[TT];
__device__ int nn_perm[NA];
// fragment-packed tf32 weights: [mat(4)][species(4)][chunk(16)][kt2(2)][ntg(32)][lane(32)][pair(2)]
__device__ uint32_t nn_wfrag[4 * TT * 16 * 4096];   // 4 MB

// ---------------- sort-by-species ----------------
__global__ void nn_init() {
    int t = threadIdx.x;
    if (t < TT) { nn_cnt[t] = 0; nn_cur[t] = 0; }
}
__global__ void nn_hist(const int* __restrict__ sp) {
    __shared__ int c[TT];
    int tid = threadIdx.x;
    if (tid < TT) c[tid] = 0;
    __syncthreads();
    int i = blockIdx.x * blockDim.x + tid;
    if (i < NA) atomicAdd(&c[sp[i]], 1);
    __syncthreads();
    if (tid < TT && c[tid] > 0) atomicAdd(&nn_cnt[tid], c[tid]);
}
__global__ void nn_prefix() {
    if (threadIdx.x == 0) {
        int a = 0;
        for (int s = 0; s < TT; s++) { nn_off[s] = a; a += nn_cnt[s]; }
        nn_off[TT] = a;
    }
}
__global__ void nn_scatter(const int* __restrict__ sp) {
    __shared__ int lc[TT];
    __shared__ int lb[TT];
    int tid = threadIdx.x;
    if (tid < TT) lc[tid] = 0;
    __syncthreads();
    int i = blockIdx.x * blockDim.x + tid;
    int s = 0, pos = 0;
    if (i < NA) { s = sp[i]; pos = atomicAdd(&lc[s], 1); }
    __syncthreads();
    if (tid < TT) {
        int n = lc[tid];
        lb[tid] = (n > 0) ? atomicAdd(&nn_cur[tid], n) : 0;
    }
    __syncthreads();
    if (i < NA) nn_perm[nn_off[s] + lb[s] + pos] = i;
}

// ---------------- helpers ----------------
__device__ __forceinline__ uint32_t f2t(float f) {
    uint32_t r;
    asm("cvt.rna.tf32.f32 %0, %1;" : "=r"(r) : "f"(f));
    return r;
}
__device__ __forceinline__ uint32_t s2u(const void* p) {
    uint32_t a;
    asm("{ .reg .u64 t; cvta.to.shared.u64 t, %1; cvt.u32.u64 %0, t; }" : "=r"(a) : "l"(p));
    return a;
}
__device__ __forceinline__ void cpa16(uint32_t d, const void* s) {
    asm volatile("cp.async.cg.shared.global [%0], [%1], 16;" :: "r"(d), "l"(s) : "memory");
}
#define CPCOMMIT() asm volatile("cp.async.commit_group;" ::: "memory")
#define CPWAIT2()  asm volatile("cp.async.wait_group 2;" ::: "memory")

__device__ __forceinline__ void mma8(float* d, const uint32_t* a, const uint32_t* b) {
    asm volatile("mma.sync.aligned.m16n8k8.row.col.f32.tf32.tf32.f32 "
                 "{%0,%1,%2,%3}, {%4,%5,%6,%7}, {%8,%9}, {%0,%1,%2,%3};"
                 : "+f"(d[0]), "+f"(d[1]), "+f"(d[2]), "+f"(d[3])
                 : "r"(a[0]), "r"(a[1]), "r"(a[2]), "r"(a[3]), "r"(b[0]), "r"(b[1]));
}
__device__ __forceinline__ float silu_s(float z) {
    return z * (1.f / (1.f + __expf(-z)));
}

// ---------------- weight prepass: round to tf32 + pack to fragment layout ----------------
__global__ void nn_prep(const float* __restrict__ W0, const float* __restrict__ Wa,
                        const float* __restrict__ Wl, const float* __restrict__ Wf) {
    int p = blockIdx.x * 256 + threadIdx.x;            // 0 .. 524287 (pairs)
    int lane = p & 31;
    int ntg  = (p >> 5) & 31;
    int kt2  = (p >> 10) & 1;
    int c    = (p >> 11) & 15;
    int s    = (p >> 15) & 3;
    int m    = p >> 17;
    const float* W = (m == 0 ? W0 : m == 1 ? Wa : m == 2 ? Wl : Wf) + s * D * D;
    int n = ntg * 8 + (lane >> 2);
    int k = c * 16 + kt2 * 8 + (lane & 3);
    nn_wfrag[2 * p]     = f2t(__ldg(W + n * D + k));
    nn_wfrag[2 * p + 1] = f2t(__ldg(W + n * D + k + 4));
}

// ---------------- staging ----------------
__device__ __forceinline__ void issue_chunk(uint32_t sB_u32, const uint32_t* wsrc, int c, int tid) {
    uint32_t dst = sB_u32 + ((c & 3) * 4096 + tid * 4) * 4;
    const uint32_t* src = wsrc + c * 4096 + tid * 4;
#pragma unroll
    for (int i = 0; i < 4; i++) cpa16(dst + i * 4096, src + i * 1024);
    CPCOMMIT();
}

// ---------------- 64x256x256 GEMM on mma.sync tf32 ----------------
__device__ __forceinline__ void gemm64(const uint32_t* __restrict__ smA,
                                       const float* __restrict__ smB,
                                       uint32_t sB_u32, const uint32_t* __restrict__ wsrc,
                                       float acc[4][4][4], int tid, int warp, int lane) {
#pragma unroll
    for (int mt = 0; mt < 4; mt++)
#pragma unroll
        for (int nt = 0; nt < 4; nt++)
#pragma unroll
            for (int q = 0; q < 4; q++) acc[mt][nt][q] = 0.f;

    const int qr = lane >> 2, qc = lane & 3;
    for (int c = 0; c < 16; c++) {
        CPWAIT2();
        __syncthreads();
        if (c < 13) issue_chunk(sB_u32, wsrc, c + 3, tid);
        else CPCOMMIT();
        const float* Bb = smB + (c & 3) * 4096;
#pragma unroll
        for (int kt = 0; kt < 2; kt++) {
            float2 bv[4];
#pragma unroll
            for (int nt = 0; nt < 4; nt++)
                bv[nt] = *(const float2*)(Bb + (kt * 1024 + (warp * 4 + nt) * 32 + lane) * 2);
            const int k0 = c * 16 + kt * 8;
            uint32_t a[4][4];
#pragma unroll
            for (int mt = 0; mt < 4; mt++) {
                const uint32_t* ap = smA + (mt * 16 + qr) * SA + k0 + qc;
                a[mt][0] = ap[0];
                a[mt][1] = ap[8 * SA];
                a[mt][2] = ap[4];
                a[mt][3] = ap[8 * SA + 4];
            }
#pragma unroll
            for (int mt = 0; mt < 4; mt++)
#pragma unroll
                for (int nt = 0; nt < 4; nt++)
                    mma8(acc[mt][nt], a[mt], (const uint32_t*)&bv[nt]);
        }
    }
}

// ---------------- fused expert MLP ----------------
__global__ void __launch_bounds__(NTH, 1)
nn_fused(const float* __restrict__ density,
         const float* __restrict__ b0, const float* __restrict__ ba,
         const float* __restrict__ alpha_a, const float* __restrict__ gamma,
         const float* __restrict__ beta_ln, const float* __restrict__ bl,
         const float* __restrict__ bf, const float* __restrict__ alpha_f,
         const float* __restrict__ Wo, const float* __restrict__ bo,
         float* __restrict__ out) {
    extern __shared__ float sm[];
    uint32_t* smA = (uint32_t*)(sm + OFF_A);
    float* smB   = sm + OFF_B;
    float* smX   = sm + OFF_X;
    float* red   = sm + OFF_RED;
    float* stats = sm + OFF_STATS;
    const uint32_t sB_u32 = s2u(smB);

    const int tid = threadIdx.x;
    const int warp = tid >> 5;
    const int lane = tid & 31;
    const int qr = lane >> 2, qc = lane & 3;
    const int row0 = blockIdx.x * TM;

    for (int s = 0; s < TT; s++) {
        const int lo = max(row0, nn_off[s]);
        const int hi = min(row0 + TM, nn_off[s + 1]);
        if (lo >= hi) continue;
        __syncthreads();

        const uint32_t* wb0 = nn_wfrag + (size_t)(0 * 4 + s) * 65536;
        const uint32_t* wb1 = nn_wfrag + (size_t)(1 * 4 + s) * 65536;
        const uint32_t* wb2 = nn_wfrag + (size_t)(2 * 4 + s) * 65536;
        const uint32_t* wb3 = nn_wfrag + (size_t)(3 * 4 + s) * 65536;
        const float* b0s = b0 + s * D;
        const float* bas = ba + s * D;
        const float* aas = alpha_a + s * D;
        const float* gs  = gamma + s * D;
        const float* bts = beta_ln + s * D;
        const float* bls = bl + s * D;
        const float* bfs = bf + s * D;
        const float* afs = alpha_f + s * D;
        const float* wos = Wo + s * D;

        // prologue for W0 + gather density
        issue_chunk(sB_u32, wb0, 0, tid);
        issue_chunk(sB_u32, wb0, 1, tid);
        issue_chunk(sB_u32, wb0, 2, tid);
#pragma unroll
        for (int it = 0; it < 16; it++) {
            int q = it * 256 + tid;
            int r = q >> 6, jc = q & 63;
            uint4 t = make_uint4(0u, 0u, 0u, 0u);
            int gr = row0 + r;
            if (gr >= lo && gr < hi) {
                float4 v = __ldg((const float4*)(density + (size_t)nn_perm[gr] * D + jc * 4));
                t = make_uint4(f2t(v.x), f2t(v.y), f2t(v.z), f2t(v.w));
            }
            *(uint4*)(smA + r * SA + jc * 4) = t;
        }

        float acc[4][4][4];

        // ===== layer 0: x = A @ W0^T + b0  (save x, write tf32(x) to A) =====
        gemm64(smA, smB, sB_u32, wb0, acc, tid, warp, lane);
        __syncthreads();
        issue_chunk(sB_u32, wb1, 0, tid);
        issue_chunk(sB_u32, wb1, 1, tid);
        issue_chunk(sB_u32, wb1, 2, tid);
#pragma unroll
        for (int mt = 0; mt < 4; mt++)
#pragma unroll
            for (int nt = 0; nt < 4; nt++) {
                const int c0 = warp * 32 + nt * 8 + 2 * qc;
                float2 b2 = __ldg((const float2*)(b0s + c0));
                float z0 = acc[mt][nt][0] + b2.x, z1 = acc[mt][nt][1] + b2.y;
                float z2 = acc[mt][nt][2] + b2.x, z3 = acc[mt][nt][3] + b2.y;
                *(float4*)(smX + (mt * 4 + nt) * 1024 + tid * 4) = make_float4(z0, z1, z2, z3);
                const int rr = mt * 16 + qr;
                *(uint2*)(smA + rr * SA + c0)       = make_uint2(f2t(z0), f2t(z1));
                *(uint2*)(smA + (rr + 8) * SA + c0) = make_uint2(f2t(z2), f2t(z3));
            }

        // ===== hidden: h = LN(alpha_a * silu(x @ Wa^T + ba)) =====
        gemm64(smA, smB, sB_u32, wb1, acc, tid, warp, lane);
        __syncthreads();
        issue_chunk(sB_u32, wb2, 0, tid);
        issue_chunk(sB_u32, wb2, 1, tid);
        issue_chunk(sB_u32, wb2, 2, tid);
        {
            float rs[8], rq[8];
#pragma unroll
            for (int i = 0; i < 8; i++) { rs[i] = 0.f; rq[i] = 0.f; }
#pragma unroll
            for (int mt = 0; mt < 4; mt++)
#pragma unroll
                for (int nt = 0; nt < 4; nt++) {
                    const int c0 = warp * 32 + nt * 8 + 2 * qc;
                    float2 b2 = __ldg((const float2*)(bas + c0));
                    float2 a2 = __ldg((const float2*)(aas + c0));
                    float h0 = a2.x * silu_s(acc[mt][nt][0] + b2.x);
                    float h1 = a2.y * silu_s(acc[mt][nt][1] + b2.y);
                    float h2 = a2.x * silu_s(acc[mt][nt][2] + b2.x);
                    float h3 = a2.y * silu_s(acc[mt][nt][3] + b2.y);
                    acc[mt][nt][0] = h0; acc[mt][nt][1] = h1;
                    acc[mt][nt][2] = h2; acc[mt][nt][3] = h3;
                    rs[mt * 2] += h0 + h1;       rq[mt * 2] += h0 * h0 + h1 * h1;
                    rs[mt * 2 + 1] += h2 + h3;   rq[mt * 2 + 1] += h2 * h2 + h3 * h3;
                }
#pragma unroll
            for (int i = 0; i < 8; i++) {
                rs[i] += __shfl_xor_sync(0xffffffffu, rs[i], 1);
                rs[i] += __shfl_xor_sync(0xffffffffu, rs[i], 2);
                rq[i] += __shfl_xor_sync(0xffffffffu, rq[i], 1);
                rq[i] += __shfl_xor_sync(0xffffffffu, rq[i], 2);
            }
            if (qc == 0) {
#pragma unroll
                for (int mt = 0; mt < 4; mt++) {
                    int r0 = mt * 16 + qr;
                    red[r0 * 8 + warp] = rs[mt * 2];
                    red[512 + r0 * 8 + warp] = rq[mt * 2];
                    red[(r0 + 8) * 8 + warp] = rs[mt * 2 + 1];
                    red[512 + (r0 + 8) * 8 + warp] = rq[mt * 2 + 1];
                }
            }
            __syncthreads();
            if (tid < 64) {
                float su = 0.f, sq = 0.f;
#pragma unroll
                for (int w = 0; w < 8; w++) { su += red[tid * 8 + w]; sq += red[512 + tid * 8 + w]; }
                float mu = su * (1.0f / D);
                stats[2 * tid] = mu;
                stats[2 * tid + 1] = rsqrtf(sq * (1.0f / D) - mu * mu + 1e-5f);
            }
            __syncthreads();
#pragma unroll
            for (int mt = 0; mt < 4; mt++) {
                const int rr = mt * 16 + qr;
                float2 st0 = *(const float2*)(stats + 2 * rr);
                float2 st1 = *(const float2*)(stats + 2 * (rr + 8));
#pragma unroll
                for (int nt = 0; nt < 4; nt++) {
                    const int c0 = warp * 32 + nt * 8 + 2 * qc;
                    float2 g2 = __ldg((const float2*)(gs + c0));
                    float2 bt2 = __ldg((const float2*)(bts + c0));
                    float n0 = g2.x * (acc[mt][nt][0] - st0.x) * st0.y + bt2.x;
                    float n1 = g2.y * (acc[mt][nt][1] - st0.x) * st0.y + bt2.y;
                    float n2 = g2.x * (acc[mt][nt][2] - st1.x) * st1.y + bt2.x;
                    float n3 = g2.y * (acc[mt][nt][3] - st1.x) * st1.y + bt2.y;
                    *(uint2*)(smA + rr * SA + c0)       = make_uint2(f2t(n0), f2t(n1));
                    *(uint2*)(smA + (rr + 8) * SA + c0) = make_uint2(f2t(n2), f2t(n3));
                }
            }
        }

        // ===== residual: y = x + h @ Wl^T + bl =====
        gemm64(smA, smB, sB_u32, wb2, acc, tid, warp, lane);
        __syncthreads();
        issue_chunk(sB_u32, wb3, 0, tid);
        issue_chunk(sB_u32, wb3, 1, tid);
        issue_chunk(sB_u32, wb3, 2, tid);
#pragma unroll
        for (int mt = 0; mt < 4; mt++)
#pragma unroll
            for (int nt = 0; nt < 4; nt++) {
                const int c0 = warp * 32 + nt * 8 + 2 * qc;
                float2 b2 = __ldg((const float2*)(bls + c0));
                float4 xv = *(const float4*)(smX + (mt * 4 + nt) * 1024 + tid * 4);
                float y0 = xv.x + acc[mt][nt][0] + b2.x;
                float y1 = xv.y + acc[mt][nt][1] + b2.y;
                float y2 = xv.z + acc[mt][nt][2] + b2.x;
                float y3 = xv.w + acc[mt][nt][3] + b2.y;
                const int rr = mt * 16 + qr;
                *(uint2*)(smA + rr * SA + c0)       = make_uint2(f2t(y0), f2t(y1));
                *(uint2*)(smA + (rr + 8) * SA + c0) = make_uint2(f2t(y2), f2t(y3));
            }

        // ===== tail: f = alpha_f * silu(y @ Wf^T + bf); out = f . Wo + bo =====
        gemm64(smA, smB, sB_u32, wb3, acc, tid, warp, lane);
        __syncthreads();
        {
            float rs[8];
#pragma unroll
            for (int i = 0; i < 8; i++) rs[i] = 0.f;
#pragma unroll
            for (int mt = 0; mt < 4; mt++)
#pragma unroll
                for (int nt = 0; nt < 4; nt++) {
                    const int c0 = warp * 32 + nt * 8 + 2 * qc;
                    float2 b2 = __ldg((const float2*)(bfs + c0));
                    float2 a2 = __ldg((const float2*)(afs + c0));
                    float2 w2 = __ldg((const float2*)(wos + c0));
                    rs[mt * 2]     += a2.x * silu_s(acc[mt][nt][0] + b2.x) * w2.x
                                    + a2.y * silu_s(acc[mt][nt][1] + b2.y) * w2.y;
                    rs[mt * 2 + 1] += a2.x * silu_s(acc[mt][nt][2] + b2.x) * w2.x
                                    + a2.y * silu_s(acc[mt][nt][3] + b2.y) * w2.y;
                }
#pragma unroll
            for (int i = 0; i < 8; i++) {
                rs[i] += __shfl_xor_sync(0xffffffffu, rs[i], 1);
                rs[i] += __shfl_xor_sync(0xffffffffu, rs[i], 2);
            }
            if (qc == 0) {
#pragma unroll
                for (int mt = 0; mt < 4; mt++) {
                    int r0 = mt * 16 + qr;
                    red[r0 * 8 + warp] = rs[mt * 2];
                    red[(r0 + 8) * 8 + warp] = rs[mt * 2 + 1];
                }
            }
            __syncthreads();
            if (tid < 64) {
                int gr = row0 + tid;
                if (gr >= lo && gr < hi) {
                    float t = 0.f;
#pragma unroll
                    for (int w = 0; w < 8; w++) t += red[tid * 8 + w];
                    out[nn_perm[gr]] = t + __ldg(bo + s);
                }
            }
        }
    }
}

// ---------------- launch ----------------
extern "C" void kernel_launch(void* const* d_in, const int* in_sizes, int n_in,
                              void* d_out, int out_size) {
    const float* density = (const float*)d_in[0];
    const int*   species = (const int*)d_in[1];
    const float* W0      = (const float*)d_in[2];
    const float* b0      = (const float*)d_in[3];
    const float* Wa      = (const float*)d_in[4];
    const float* ba      = (const float*)d_in[5];
    const float* alpha_a = (const float*)d_in[6];
    const float* gamma   = (const float*)d_in[7];
    const float* beta_ln = (const float*)d_in[8];
    const float* Wl      = (const float*)d_in[9];
    const float* bl      = (const float*)d_in[10];
    const float* Wf      = (const float*)d_in[11];
    const float* bf      = (const float*)d_in[12];
    const float* alpha_f = (const float*)d_in[13];
    const float* Wo      = (const float*)d_in[14];
    const float* bo      = (const float*)d_in[15];
    float* out = (float*)d_out;

    cudaFuncSetAttribute(nn_fused, cudaFuncAttributeMaxDynamicSharedMemorySize, SMEM_BYTES);

    nn_init<<<1, 32>>>();
    nn_hist<<<NA / 256, 256>>>(species);
    nn_prefix<<<1, 1>>>();
    nn_scatter<<<NA / 256, 256>>>(species);
    nn_prep<<<2048, 256>>>(W0, Wa, Wl, Wf);
    nn_fused<<<NTILES, NTH, SMEM_BYTES>>>(density, b0, ba, alpha_a, gamma, beta_ln,
                                          bl, bf, alpha_f, Wo, bo, out);
}

// round 4
// speedup vs baseline: 4.1877x; 1.4489x over previous
#include <cuda_runtime.h>
#include <cuda_fp16.h>
#include <cstdint>

#define NA 65536
#define D  256
#define TT 4
#define TM 64
#define NTILES (NA / TM)   // 1024
#define NTH 256
#define SAW 132            // A row stride in u32 (264 halves) -> conflict-free frags

// ---- shared memory byte offsets ----
#define OFF_A_B   0                      // A tile fp16: 64 x 132 u32 = 33792 B
#define OFF_B_B   33792                  // B chunk ring: 4 x 8192 B = 32768
#define OFF_RED_B 66560                  // 1024 floats = 4096 B
#define OFF_ST_B  70656                  // 128 floats mu/inv
#define SMEM_BYTES 71680

// ---------------- device scratch ----------------
__device__ int nn_off[TT + 1];
__device__ int nn_cnt[TT];
__device__ int nn_cur[TT];
__device__ int nn_perm[NA];
// fp16 fragment-packed weights: [mat(4)][species(4)][chunk(16)][g(32)][lane(32)][2xu32] = 2MB
__device__ __align__(16) uint32_t nn_wfragh[4 * TT * 16 * 2048];

// ---------------- sort-by-species ----------------
__global__ void nn_init() {
    int t = threadIdx.x;
    if (t < TT) { nn_cnt[t] = 0; nn_cur[t] = 0; }
}
__global__ void nn_hist(const int* __restrict__ sp) {
    __shared__ int c[TT];
    int tid = threadIdx.x;
    if (tid < TT) c[tid] = 0;
    __syncthreads();
    int i = blockIdx.x * blockDim.x + tid;
    if (i < NA) atomicAdd(&c[sp[i]], 1);
    __syncthreads();
    if (tid < TT && c[tid] > 0) atomicAdd(&nn_cnt[tid], c[tid]);
}
__global__ void nn_prefix() {
    if (threadIdx.x == 0) {
        int a = 0;
        for (int s = 0; s < TT; s++) { nn_off[s] = a; a += nn_cnt[s]; }
        nn_off[TT] = a;
    }
}
__global__ void nn_scatter(const int* __restrict__ sp) {
    __shared__ int lc[TT];
    __shared__ int lb[TT];
    int tid = threadIdx.x;
    if (tid < TT) lc[tid] = 0;
    __syncthreads();
    int i = blockIdx.x * blockDim.x + tid;
    int s = 0, pos = 0;
    if (i < NA) { s = sp[i]; pos = atomicAdd(&lc[s], 1); }
    __syncthreads();
    if (tid < TT) {
        int n = lc[tid];
        lb[tid] = (n > 0) ? atomicAdd(&nn_cur[tid], n) : 0;
    }
    __syncthreads();
    if (i < NA) nn_perm[nn_off[s] + lb[s] + pos] = i;
}

// ---------------- helpers ----------------
__device__ __forceinline__ uint32_t h2u(float a, float b) {
    __half2 h = __floats2half2_rn(a, b);
    return *(uint32_t*)&h;
}
__device__ __forceinline__ uint32_t s2u(const void* p) {
    uint32_t a;
    asm("{ .reg .u64 t; cvta.to.shared.u64 t, %1; cvt.u32.u64 %0, t; }" : "=r"(a) : "l"(p));
    return a;
}
__device__ __forceinline__ void cpa16(uint32_t d, const void* s) {
    asm volatile("cp.async.cg.shared.global [%0], [%1], 16;" :: "r"(d), "l"(s) : "memory");
}
#define CPCOMMIT() asm volatile("cp.async.commit_group;" ::: "memory")
#define CPWAIT2()  asm volatile("cp.async.wait_group 2;" ::: "memory")

__device__ __forceinline__ void mma16(float* d, const uint32_t* a, const uint32_t* b) {
    asm volatile("mma.sync.aligned.m16n8k16.row.col.f32.f16.f16.f32 "
                 "{%0,%1,%2,%3}, {%4,%5,%6,%7}, {%8,%9}, {%0,%1,%2,%3};"
                 : "+f"(d[0]), "+f"(d[1]), "+f"(d[2]), "+f"(d[3])
                 : "r"(a[0]), "r"(a[1]), "r"(a[2]), "r"(a[3]), "r"(b[0]), "r"(b[1]));
}
__device__ __forceinline__ float silu_s(float z) {
    return z * (1.f / (1.f + __expf(-z)));
}

// ---------------- weight prepass: fp16 fragment packing ----------------
// frag for mma.m16n8k16 B (col): b0={B[2t][g8+q], B[2t+1][..]}, b1={B[2t+8][..], B[2t+9][..]}
__global__ void nn_prep(const float* __restrict__ W0, const float* __restrict__ Wa,
                        const float* __restrict__ Wl, const float* __restrict__ Wf) {
    int p = blockIdx.x * 256 + threadIdx.x;      // 0..262143 lane-frags
    int l = p & 31;
    int g = (p >> 5) & 31;
    int c = (p >> 10) & 15;
    int s = (p >> 14) & 3;
    int m = p >> 16;
    const float* W = (m == 0 ? W0 : m == 1 ? Wa : m == 2 ? Wl : Wf) + s * D * D;
    int n  = g * 8 + (l >> 2);
    int k0 = c * 16 + (l & 3) * 2;
    const float* wr = W + n * D;
    nn_wfragh[2 * p]     = h2u(__ldg(wr + k0),     __ldg(wr + k0 + 1));
    nn_wfragh[2 * p + 1] = h2u(__ldg(wr + k0 + 8), __ldg(wr + k0 + 9));
}

// ---------------- staging: one 8KB chunk (k16 x n256 fragments) ----------------
__device__ __forceinline__ void issue_chunk(uint32_t sB_u32, const uint4* wsrc, int c, int tid) {
    uint32_t dst = sB_u32 + (uint32_t)((c & 3) * 8192 + tid * 32);
    const uint4* src = wsrc + c * 512 + tid * 2;
    cpa16(dst, src);
    cpa16(dst + 16, src + 1);
    CPCOMMIT();
}

// ---------------- 64x256x256 GEMM on mma.sync fp16 (acc NOT zeroed here) ----------------
__device__ __forceinline__ void gemm64(const uint32_t* __restrict__ smA,
                                       const uint32_t* __restrict__ smB,
                                       uint32_t sB_u32, const uint4* __restrict__ wsrc,
                                       float acc[4][4][4], int tid, int warp, int lane) {
    const int qr = lane >> 2, qc = lane & 3;
    for (int c = 0; c < 16; c++) {
        CPWAIT2();
        __syncthreads();
        if (c < 13) issue_chunk(sB_u32, wsrc, c + 3, tid);
        else CPCOMMIT();
        const uint32_t* Bb = smB + (c & 3) * 2048;
        uint2 bv[4];
#pragma unroll
        for (int nt = 0; nt < 4; nt++)
            bv[nt] = *(const uint2*)(Bb + ((warp * 4 + nt) * 32 + lane) * 2);
        uint32_t a[4][4];
#pragma unroll
        for (int mt = 0; mt < 4; mt++) {
            const uint32_t* ap = smA + (mt * 16 + qr) * SAW + c * 8 + qc;
            a[mt][0] = ap[0];
            a[mt][1] = ap[8 * SAW];
            a[mt][2] = ap[4];
            a[mt][3] = ap[8 * SAW + 4];
        }
#pragma unroll
        for (int mt = 0; mt < 4; mt++)
#pragma unroll
            for (int nt = 0; nt < 4; nt++)
                mma16(acc[mt][nt], a[mt], (const uint32_t*)&bv[nt]);
    }
}

#define ZACC(acc) \
    _Pragma("unroll") for (int mt = 0; mt < 4; mt++) \
    _Pragma("unroll") for (int nt = 0; nt < 4; nt++) \
    _Pragma("unroll") for (int q = 0; q < 4; q++) (acc)[mt][nt][q] = 0.f;

// ---------------- fused expert MLP ----------------
__global__ void __launch_bounds__(NTH, 1)
nn_fused(const float* __restrict__ density,
         const float* __restrict__ b0, const float* __restrict__ ba,
         const float* __restrict__ alpha_a, const float* __restrict__ gamma,
         const float* __restrict__ beta_ln, const float* __restrict__ bl,
         const float* __restrict__ bf, const float* __restrict__ alpha_f,
         const float* __restrict__ Wo, const float* __restrict__ bo,
         float* __restrict__ out) {
    extern __shared__ char smraw[];
    uint32_t* smA  = (uint32_t*)(smraw + OFF_A_B);
    uint32_t* smB  = (uint32_t*)(smraw + OFF_B_B);
    float*    red  = (float*)(smraw + OFF_RED_B);
    float*    stats = (float*)(smraw + OFF_ST_B);
    const uint32_t sB_u32 = s2u(smB);

    const int tid = threadIdx.x;
    const int warp = tid >> 5;
    const int lane = tid & 31;
    const int qr = lane >> 2, qc = lane & 3;
    const int row0 = blockIdx.x * TM;

    for (int s = 0; s < TT; s++) {
        const int lo = max(row0, nn_off[s]);
        const int hi = min(row0 + TM, nn_off[s + 1]);
        if (lo >= hi) continue;
        __syncthreads();

        const uint4* wb0 = (const uint4*)(nn_wfragh + (size_t)(0 * 4 + s) * 32768);
        const uint4* wb1 = (const uint4*)(nn_wfragh + (size_t)(1 * 4 + s) * 32768);
        const uint4* wb2 = (const uint4*)(nn_wfragh + (size_t)(2 * 4 + s) * 32768);
        const uint4* wb3 = (const uint4*)(nn_wfragh + (size_t)(3 * 4 + s) * 32768);
        const float* b0s = b0 + s * D;
        const float* bas = ba + s * D;
        const float* aas = alpha_a + s * D;
        const float* gs  = gamma + s * D;
        const float* bts = beta_ln + s * D;
        const float* bls = bl + s * D;
        const float* bfs = bf + s * D;
        const float* afs = alpha_f + s * D;
        const float* wos = Wo + s * D;

        // prologue for W0 + gather density (fp16 into A)
        issue_chunk(sB_u32, wb0, 0, tid);
        issue_chunk(sB_u32, wb0, 1, tid);
        issue_chunk(sB_u32, wb0, 2, tid);
#pragma unroll
        for (int it = 0; it < 16; it++) {
            int q = it * 256 + tid;          // 0..4095 float4 slots
            int r = q >> 6, j = q & 63;      // row, float4-col
            uint2 t = make_uint2(0u, 0u);
            int gr = row0 + r;
            if (gr >= lo && gr < hi) {
                float4 v = __ldg((const float4*)(density + (size_t)nn_perm[gr] * D + j * 4));
                t = make_uint2(h2u(v.x, v.y), h2u(v.z, v.w));
            }
            *(uint2*)(smA + r * SAW + j * 2) = t;
        }

        float acc[4][4][4];
        float xsave[4][4][4];

        // ===== layer 0: x = A @ W0^T + b0 (x kept in regs, fp16(x) -> A) =====
        ZACC(acc);
        gemm64(smA, smB, sB_u32, wb0, acc, tid, warp, lane);
        __syncthreads();
        issue_chunk(sB_u32, wb1, 0, tid);
        issue_chunk(sB_u32, wb1, 1, tid);
        issue_chunk(sB_u32, wb1, 2, tid);
#pragma unroll
        for (int mt = 0; mt < 4; mt++)
#pragma unroll
            for (int nt = 0; nt < 4; nt++) {
                const int c0 = warp * 32 + nt * 8 + 2 * qc;
                float2 b2 = __ldg((const float2*)(b0s + c0));
                float z0 = acc[mt][nt][0] + b2.x, z1 = acc[mt][nt][1] + b2.y;
                float z2 = acc[mt][nt][2] + b2.x, z3 = acc[mt][nt][3] + b2.y;
                xsave[mt][nt][0] = z0; xsave[mt][nt][1] = z1;
                xsave[mt][nt][2] = z2; xsave[mt][nt][3] = z3;
                const int rr = mt * 16 + qr, cw = warp * 16 + nt * 4 + qc;
                smA[rr * SAW + cw]       = h2u(z0, z1);
                smA[(rr + 8) * SAW + cw] = h2u(z2, z3);
            }

        // ===== hidden: h = LN(alpha_a * silu(x @ Wa^T + ba)) -> A =====
        ZACC(acc);
        gemm64(smA, smB, sB_u32, wb1, acc, tid, warp, lane);
        __syncthreads();
        issue_chunk(sB_u32, wb2, 0, tid);
        issue_chunk(sB_u32, wb2, 1, tid);
        issue_chunk(sB_u32, wb2, 2, tid);
        {
            float rs[8], rq[8];
#pragma unroll
            for (int i = 0; i < 8; i++) { rs[i] = 0.f; rq[i] = 0.f; }
#pragma unroll
            for (int mt = 0; mt < 4; mt++)
#pragma unroll
                for (int nt = 0; nt < 4; nt++) {
                    const int c0 = warp * 32 + nt * 8 + 2 * qc;
                    float2 b2 = __ldg((const float2*)(bas + c0));
                    float2 a2 = __ldg((const float2*)(aas + c0));
                    float h0 = a2.x * silu_s(acc[mt][nt][0] + b2.x);
                    float h1 = a2.y * silu_s(acc[mt][nt][1] + b2.y);
                    float h2 = a2.x * silu_s(acc[mt][nt][2] + b2.x);
                    float h3 = a2.y * silu_s(acc[mt][nt][3] + b2.y);
                    acc[mt][nt][0] = h0; acc[mt][nt][1] = h1;
                    acc[mt][nt][2] = h2; acc[mt][nt][3] = h3;
                    rs[mt * 2] += h0 + h1;       rq[mt * 2] += h0 * h0 + h1 * h1;
                    rs[mt * 2 + 1] += h2 + h3;   rq[mt * 2 + 1] += h2 * h2 + h3 * h3;
                }
#pragma unroll
            for (int i = 0; i < 8; i++) {
                rs[i] += __shfl_xor_sync(0xffffffffu, rs[i], 1);
                rs[i] += __shfl_xor_sync(0xffffffffu, rs[i], 2);
                rq[i] += __shfl_xor_sync(0xffffffffu, rq[i], 1);
                rq[i] += __shfl_xor_sync(0xffffffffu, rq[i], 2);
            }
            if (qc == 0) {
#pragma unroll
                for (int mt = 0; mt < 4; mt++) {
                    int r0 = mt * 16 + qr;
                    red[r0 * 8 + warp] = rs[mt * 2];
                    red[512 + r0 * 8 + warp] = rq[mt * 2];
                    red[(r0 + 8) * 8 + warp] = rs[mt * 2 + 1];
                    red[512 + (r0 + 8) * 8 + warp] = rq[mt * 2 + 1];
                }
            }
            __syncthreads();
            if (tid < 64) {
                float su = 0.f, sq = 0.f;
#pragma unroll
                for (int w = 0; w < 8; w++) { su += red[tid * 8 + w]; sq += red[512 + tid * 8 + w]; }
                float mu = su * (1.0f / D);
                stats[2 * tid] = mu;
                stats[2 * tid + 1] = rsqrtf(sq * (1.0f / D) - mu * mu + 1e-5f);
            }
            __syncthreads();
#pragma unroll
            for (int mt = 0; mt < 4; mt++) {
                const int rr = mt * 16 + qr;
                float2 st0 = *(const float2*)(stats + 2 * rr);
                float2 st1 = *(const float2*)(stats + 2 * (rr + 8));
#pragma unroll
                for (int nt = 0; nt < 4; nt++) {
                    const int c0 = warp * 32 + nt * 8 + 2 * qc;
                    float2 g2 = __ldg((const float2*)(gs + c0));
                    float2 bt2 = __ldg((const float2*)(bts + c0));
                    float n0 = g2.x * (acc[mt][nt][0] - st0.x) * st0.y + bt2.x;
                    float n1 = g2.y * (acc[mt][nt][1] - st0.x) * st0.y + bt2.y;
                    float n2 = g2.x * (acc[mt][nt][2] - st1.x) * st1.y + bt2.x;
                    float n3 = g2.y * (acc[mt][nt][3] - st1.x) * st1.y + bt2.y;
                    const int cw = warp * 16 + nt * 4 + qc;
                    smA[rr * SAW + cw]       = h2u(n0, n1);
                    smA[(rr + 8) * SAW + cw] = h2u(n2, n3);
                }
            }
        }

        // ===== residual: y = x + h @ Wl^T + bl (acc seeded with xsave) =====
#pragma unroll
        for (int mt = 0; mt < 4; mt++)
#pragma unroll
            for (int nt = 0; nt < 4; nt++)
#pragma unroll
                for (int q = 0; q < 4; q++) acc[mt][nt][q] = xsave[mt][nt][q];
        gemm64(smA, smB, sB_u32, wb2, acc, tid, warp, lane);
        __syncthreads();
        issue_chunk(sB_u32, wb3, 0, tid);
        issue_chunk(sB_u32, wb3, 1, tid);
        issue_chunk(sB_u32, wb3, 2, tid);
#pragma unroll
        for (int mt = 0; mt < 4; mt++)
#pragma unroll
            for (int nt = 0; nt < 4; nt++) {
                const int c0 = warp * 32 + nt * 8 + 2 * qc;
                float2 b2 = __ldg((const float2*)(bls + c0));
                float y0 = acc[mt][nt][0] + b2.x, y1 = acc[mt][nt][1] + b2.y;
                float y2 = acc[mt][nt][2] + b2.x, y3 = acc[mt][nt][3] + b2.y;
                const int rr = mt * 16 + qr, cw = warp * 16 + nt * 4 + qc;
                smA[rr * SAW + cw]       = h2u(y0, y1);
                smA[(rr + 8) * SAW + cw] = h2u(y2, y3);
            }

        // ===== tail: f = alpha_f * silu(y @ Wf^T + bf); out = f . Wo + bo =====
        ZACC(acc);
        gemm64(smA, smB, sB_u32, wb3, acc, tid, warp, lane);
        __syncthreads();
        {
            float rs[8];
#pragma unroll
            for (int i = 0; i < 8; i++) rs[i] = 0.f;
#pragma unroll
            for (int mt = 0; mt < 4; mt++)
#pragma unroll
                for (int nt = 0; nt < 4; nt++) {
                    const int c0 = warp * 32 + nt * 8 + 2 * qc;
                    float2 b2 = __ldg((const float2*)(bfs + c0));
                    float2 a2 = __ldg((const float2*)(afs + c0));
                    float2 w2 = __ldg((const float2*)(wos + c0));
                    rs[mt * 2]     += a2.x * silu_s(acc[mt][nt][0] + b2.x) * w2.x
                                    + a2.y * silu_s(acc[mt][nt][1] + b2.y) * w2.y;
                    rs[mt * 2 + 1] += a2.x * silu_s(acc[mt][nt][2] + b2.x) * w2.x
                                    + a2.y * silu_s(acc[mt][nt][3] + b2.y) * w2.y;
                }
#pragma unroll
            for (int i = 0; i < 8; i++) {
                rs[i] += __shfl_xor_sync(0xffffffffu, rs[i], 1);
                rs[i] += __shfl_xor_sync(0xffffffffu, rs[i], 2);
            }
            if (qc == 0) {
#pragma unroll
                for (int mt = 0; mt < 4; mt++) {
                    int r0 = mt * 16 + qr;
                    red[r0 * 8 + warp] = rs[mt * 2];
                    red[(r0 + 8) * 8 + warp] = rs[mt * 2 + 1];
                }
            }
            __syncthreads();
            if (tid < 64) {
                int gr = row0 + tid;
                if (gr >= lo && gr < hi) {
                    float t = 0.f;
#pragma unroll
                    for (int w = 0; w < 8; w++) t += red[tid * 8 + w];
                    out[nn_perm[gr]] = t + __ldg(bo + s);
                }
            }
        }
    }
}

// ---------------- launch ----------------
extern "C" void kernel_launch(void* const* d_in, const int* in_sizes, int n_in,
                              void* d_out, int out_size) {
    const float* density = (const float*)d_in[0];
    const int*   species = (const int*)d_in[1];
    const float* W0      = (const float*)d_in[2];
    const float* b0      = (const float*)d_in[3];
    const float* Wa      = (const float*)d_in[4];
    const float* ba      = (const float*)d_in[5];
    const float* alpha_a = (const float*)d_in[6];
    const float* gamma   = (const float*)d_in[7];
    const float* beta_ln = (const float*)d_in[8];
    const float* Wl      = (const float*)d_in[9];
    const float* bl      = (const float*)d_in[10];
    const float* Wf      = (const float*)d_in[11];
    const float* bf      = (const float*)d_in[12];
    const float* alpha_f = (const float*)d_in[13];
    const float* Wo      = (const float*)d_in[14];
    const float* bo      = (const float*)d_in[15];
    float* out = (float*)d_out;

    cudaFuncSetAttribute(nn_fused, cudaFuncAttributeMaxDynamicSharedMemorySize, SMEM_BYTES);

    nn_init<<<1, 32>>>();
    nn_hist<<<NA / 256, 256>>>(species);
    nn_prefix<<<1, 1>>>();
    nn_scatter<<<NA / 256, 256>>>(species);
    nn_prep<<<1024, 256>>>(W0, Wa, Wl, Wf);
    nn_fused<<<NTILES, NTH, SMEM_BYTES>>>(density, b0, ba, alpha_a, gamma, beta_ln,
                                          bl, bf, alpha_f, Wo, bo, out);
}